// round 7
// baseline (speedup 1.0000x reference)
#include <cuda_runtime.h>
#include <cuda_fp16.h>
#include <math.h>
#include <stdint.h>

// ---------------------------------------------------------------------------
// HaplotypeEmbedding, fp16 + mma.sync m16n8k16 + ldmatrix, lean producer:
//   - P[l][v][:] = tables[l][v] @ W1_l + b1/8   fp16 (4.2 MB, L2-resident)
//   - branchless A&S-7.1.25 gelu (abs err < 3e-5)
//   - chunk-invariant gather offsets held in registers
// ---------------------------------------------------------------------------

#define L_    8
#define V_    512
#define D_    256
#define HID_  512
#define NOUT_ 256
#define NTOT  131072
#define MTILE 64
#define NBLK  (NTOT / MTILE)   // 2048
#define KCH   64
#define NCH   (HID_ / KCH)     // 8

#define SAH 72
#define SBH 72
#define SA_BUFH (MTILE * SAH)
#define SB_BUFH (NOUT_ * SBH)

#define SM_TOK_B 0
#define SM_A_B   2048
#define SM_B_B   (SM_A_B + 2 * SA_BUFH * 2)
#define SMEM_BYTES (SM_B_B + 2 * SB_BUFH * 2)   // 94208

__device__ __half g_Ph[L_ * V_ * HID_];
__device__ __half g_W2T[NOUT_ * HID_];
__device__ int    g_is64;

// branchless gelu: x*Phi(x), erf via A&S 7.1.25 (|eps|<=2.5e-5)
__device__ __forceinline__ float gelu_fast(float x) {
    float ax = fabsf(x);
    float z  = 0.70710678118f * ax;
    float t  = __fdividef(1.0f, fmaf(0.47047f, z, 1.0f));
    float q  = fmaf(fmaf(0.7478556f, t, -0.0958798f), t, 0.3480242f) * t;
    float e  = __expf(-z * z);
    float er = fmaf(-q, e, 1.0f);              // erf(|x|/sqrt2)
    return fmaf(0.5f * ax, er, 0.5f * x);
}
__device__ __forceinline__ void mma_f16(float* d, const uint32_t* a,
                                        uint32_t b0, uint32_t b1) {
    asm volatile(
        "mma.sync.aligned.m16n8k16.row.col.f32.f16.f16.f32 "
        "{%0,%1,%2,%3}, {%4,%5,%6,%7}, {%8,%9}, {%0,%1,%2,%3};"
        : "+f"(d[0]), "+f"(d[1]), "+f"(d[2]), "+f"(d[3])
        : "r"(a[0]), "r"(a[1]), "r"(a[2]), "r"(a[3]), "r"(b0), "r"(b1));
}
__device__ __forceinline__ void ldsm4(uint32_t& r0, uint32_t& r1,
                                      uint32_t& r2, uint32_t& r3, uint32_t a) {
    asm volatile("ldmatrix.sync.aligned.m8n8.x4.shared.b16 {%0,%1,%2,%3}, [%4];"
                 : "=r"(r0), "=r"(r1), "=r"(r2), "=r"(r3) : "r"(a));
}

// ---------------------------------------------------------------------------
// Fused prolog: P projection (+ b1/8) + W2 transpose + dtype detect.
__global__ void __launch_bounds__(512) precompute_kernel(
        const float* __restrict__ tables, const float* __restrict__ W1,
        const float* __restrict__ b1, const float* __restrict__ W2,
        const unsigned int* __restrict__ hap) {
    __shared__ float4 sT4[16 * 64];
    const int l  = blockIdx.x >> 5;
    const int v0 = (blockIdx.x & 31) << 4;
    const int j  = threadIdx.x;

    {
        int gidx = blockIdx.x * 512 + j;
        int k = gidx >> 8, n = gidx & 255;
        g_W2T[n * HID_ + k] = __float2half_rn(W2[gidx]);
    }
    if (blockIdx.x == 0 && j == 0) {
        int ok = 1;
        for (int i = 0; i < 64; i++) ok &= (hap[2 * i + 1] == 0u);
        g_is64 = ok;
    }

    const float4* tsrc = (const float4*)(tables + (l * V_ + v0) * D_);
    sT4[j]       = tsrc[j];
    sT4[j + 512] = tsrc[j + 512];
    __syncthreads();

    const float b1v = 0.125f * b1[j];
    float acc[16];
#pragma unroll
    for (int r = 0; r < 16; r++) acc[r] = b1v;
    const float* w1p = W1 + (l * D_) * HID_ + j;
#pragma unroll 4
    for (int dq = 0; dq < 64; dq++) {
        float w0 = w1p[(4 * dq + 0) * HID_];
        float w1 = w1p[(4 * dq + 1) * HID_];
        float w2 = w1p[(4 * dq + 2) * HID_];
        float w3 = w1p[(4 * dq + 3) * HID_];
#pragma unroll
        for (int r = 0; r < 16; r++) {
            float4 t = sT4[r * 64 + dq];
            acc[r] += w0 * t.x; acc[r] += w1 * t.y;
            acc[r] += w2 * t.z; acc[r] += w3 * t.w;
        }
    }
#pragma unroll
    for (int r = 0; r < 16; r++)
        g_Ph[(l * V_ + v0 + r) * HID_ + j] = __float2half_rn(acc[r]);
}

// ---------------------------------------------------------------------------
__global__ void __launch_bounds__(256, 2) main_kernel(
        const unsigned int* __restrict__ hap,
        const float* __restrict__ b2,
        float* __restrict__ out) {
    extern __shared__ char smem[];
    int*    sTok = (int*)(smem + SM_TOK_B);
    __half* sA   = (__half*)(smem + SM_A_B);
    __half* sB   = (__half*)(smem + SM_B_B);
    const uint32_t sbA = (uint32_t)__cvta_generic_to_shared(sA);
    const uint32_t sbB = (uint32_t)__cvta_generic_to_shared(sB);

    const int tid = threadIdx.x, warp = tid >> 5, lane = tid & 31;
    const int is64 = g_is64;

    {
        long gbase = (long)blockIdx.x * (MTILE * L_);
#pragma unroll
        for (int i = 0; i < 2; i++) {
            int idx = tid + 256 * i;
            long gi = gbase + idx;
            int v = is64 ? (int)hap[2 * gi] : (int)hap[gi];
            v = v < 0 ? 0 : (v > V_ - 1 ? V_ - 1 : v);
            sTok[idx] = v;
        }
    }

    float acc[2][8][4];
#pragma unroll
    for (int mt = 0; mt < 2; mt++)
#pragma unroll
        for (int j = 0; j < 8; j++)
#pragma unroll
            for (int q = 0; q < 4; q++) acc[mt][j][q] = 0.f;

    const int c  = lane & 7;
    const int r  = lane >> 3;
    const int m0 = (warp >> 2) * 32;
    const int n0 = (warp & 3) * 64;
    const int bn = tid >> 3;
    const int bc = tid & 7;

    const uint32_t aoff0 = ((uint32_t)(m0 + ((lane >> 3) & 1) * 8 + (lane & 7)) * SAH +
                            (uint32_t)(lane >> 4) * 8) * 2;
    const uint32_t boff0 = ((uint32_t)(n0 + (lane >> 4) * 8 + (lane & 7)) * SBH +
                            (uint32_t)((lane >> 3) & 1) * 8) * 2;

    __syncthreads();

    // chunk-invariant gather byte-offsets (row stride 1024B)
    const char* pB = (const char*)g_Ph;
    uint32_t offs[2][8];
#pragma unroll
    for (int it = 0; it < 2; it++) {
        int m = it * 32 + warp * 4 + r;
#pragma unroll
        for (int l = 0; l < L_; l++)
            offs[it][l] = (uint32_t)(((l * V_ + sTok[m * L_ + l]) << 10) + c * 16);
    }

    // ---------------- producer ----------------
    auto produce = [&](int kt, int buf) {
        const uint32_t kb = (uint32_t)(kt * KCH * 2);
        __half* A = sA + buf * SA_BUFH;
        __half* B = sB + buf * SB_BUFH;
#pragma unroll
        for (int i = 0; i < 8; i++) {
            int n = bn + i * 32;
            uint4 v = *(const uint4*)(g_W2T + n * HID_ + kt * KCH + bc * 8);
            *(uint4*)(B + n * SBH + bc * 8) = v;
        }
#pragma unroll
        for (int it = 0; it < 2; it++) {
            int m = it * 32 + warp * 4 + r;
            float2 a0 = make_float2(0.f, 0.f), a1 = a0, a2 = a0, a3 = a0;
#pragma unroll
            for (int lp = 0; lp < 4; lp++) {
                const uint4 u = *(const uint4*)(pB + offs[it][2 * lp] + kb);
                const uint4 w = *(const uint4*)(pB + offs[it][2 * lp + 1] + kb);
                __half2 t; float2 p;
                t = __hadd2(*(const __half2*)&u.x, *(const __half2*)&w.x);
                p = __half22float2(t); a0.x += p.x; a0.y += p.y;
                t = __hadd2(*(const __half2*)&u.y, *(const __half2*)&w.y);
                p = __half22float2(t); a1.x += p.x; a1.y += p.y;
                t = __hadd2(*(const __half2*)&u.z, *(const __half2*)&w.z);
                p = __half22float2(t); a2.x += p.x; a2.y += p.y;
                t = __hadd2(*(const __half2*)&u.w, *(const __half2*)&w.w);
                p = __half22float2(t); a3.x += p.x; a3.y += p.y;
            }
            __half2 h0 = __floats2half2_rn(gelu_fast(a0.x), gelu_fast(a0.y));
            __half2 h1 = __floats2half2_rn(gelu_fast(a1.x), gelu_fast(a1.y));
            __half2 h2 = __floats2half2_rn(gelu_fast(a2.x), gelu_fast(a2.y));
            __half2 h3 = __floats2half2_rn(gelu_fast(a3.x), gelu_fast(a3.y));
            uint4 pk;
            pk.x = *(uint32_t*)&h0; pk.y = *(uint32_t*)&h1;
            pk.z = *(uint32_t*)&h2; pk.w = *(uint32_t*)&h3;
            *(uint4*)(A + m * SAH + c * 8) = pk;
        }
    };

    // ---------------- consumer ----------------
    auto consume = [&](int buf) {
        const uint32_t aB = sbA + buf * SA_BUFH * 2 + aoff0;
        const uint32_t bB = sbB + buf * SB_BUFH * 2 + boff0;
#pragma unroll
        for (int ks = 0; ks < 4; ks++) {
            uint32_t a[2][4];
#pragma unroll
            for (int mt = 0; mt < 2; mt++)
                ldsm4(a[mt][0], a[mt][1], a[mt][2], a[mt][3],
                      aB + (uint32_t)(mt * 16 * SAH * 2) + (uint32_t)(ks * 32));
#pragma unroll
            for (int jp = 0; jp < 4; jp++) {
                uint32_t b0, b1r, b2r, b3r;
                ldsm4(b0, b1r, b2r, b3r,
                      bB + (uint32_t)(jp * 16 * SBH * 2) + (uint32_t)(ks * 32));
                mma_f16(acc[0][2 * jp],     a[0], b0, b1r);
                mma_f16(acc[1][2 * jp],     a[1], b0, b1r);
                mma_f16(acc[0][2 * jp + 1], a[0], b2r, b3r);
                mma_f16(acc[1][2 * jp + 1], a[1], b2r, b3r);
            }
        }
    };

    produce(0, 0);
    __syncthreads();
#pragma unroll 1
    for (int kt = 0; kt < NCH; kt++) {
        const int buf = kt & 1;
        if (kt + 1 < NCH) produce(kt + 1, buf ^ 1);
        consume(buf);
        __syncthreads();
    }

    // ---------------- epilogue ----------------
    const float2* b2p = (const float2*)b2;
    float2* o2 = (float2*)out;
#pragma unroll
    for (int mt = 0; mt < 2; mt++) {
        size_t r0 = (size_t)blockIdx.x * MTILE + m0 + mt * 16 + (lane >> 2);
#pragma unroll
        for (int j = 0; j < 8; j++) {
            int cc = n0 / 2 + 4 * j + (lane & 3);
            float2 bv = __ldg(&b2p[cc]);
            float2 v0 = make_float2(acc[mt][j][0] + bv.x,
                                    acc[mt][j][1] + bv.y);
            float2 v1 = make_float2(acc[mt][j][2] + bv.x,
                                    acc[mt][j][3] + bv.y);
            o2[r0 * 128 + cc]       = v0;
            o2[(r0 + 8) * 128 + cc] = v1;
        }
    }
}

// ---------------------------------------------------------------------------
extern "C" void kernel_launch(void* const* d_in, const int* in_sizes, int n_in,
                              void* d_out, int out_size) {
    const unsigned int* hap    = (const unsigned int*)d_in[0];
    const float*        tables = (const float*)d_in[1];
    const float*        W1     = (const float*)d_in[2];
    const float*        b1     = (const float*)d_in[3];
    const float*        W2     = (const float*)d_in[4];
    const float*        b2     = (const float*)d_in[5];
    float*              out    = (float*)d_out;

    cudaFuncSetAttribute(main_kernel,
                         cudaFuncAttributeMaxDynamicSharedMemorySize, SMEM_BYTES);

    precompute_kernel<<<L_ * 32, 512>>>(tables, W1, b1, W2, hap);
    main_kernel<<<NBLK, 256, SMEM_BYTES>>>(hap, b2, out);
}